// round 9
// baseline (speedup 1.0000x reference)
#include <cuda_runtime.h>
#include <cuda_bf16.h>
#include <math.h>

#define SL 50
#define TL 50
#define BA 16
#define HID 1024
#define HD2 512
#define NL 4
#define VOUT 32000

__device__ __align__(16) float g_encx [SL*BA*HID];
__device__ __align__(16) float g_ency [SL*BA*HID];
__device__ __align__(16) float g_encxg[SL*BA*4096];
__device__ __align__(16) float g_enchA[2*BA*HD2];
__device__ __align__(16) float g_enchB[2*BA*HD2];
__device__ __align__(16) float g_encc [2*BA*HD2];
__device__ __align__(16) float g_h0   [NL*BA*HID];
__device__ __align__(16) float g_c0   [NL*BA*HID];
__device__ __align__(16) float g_demb [TL*BA*HID];
__device__ __align__(16) float g_pre0 [TL*BA*4096];
__device__ __align__(16) float g_dhA  [NL*BA*HID];
__device__ __align__(16) float g_dhB  [NL*BA*HID];
__device__ __align__(16) float g_dc   [NL*BA*HID];
__device__ __align__(16) float g_htl  [BA*HID];
__device__ __align__(16) float g_ctx  [BA*HID];
__device__ __align__(16) float g_hA   [SL*BA*HID];
__device__ __align__(16) float g_hbt  [TL*BA*HID];   // [t][b][H]
__device__ __align__(16) float g_part [16*4096*16];
#define OFF_W0H 0L
#define OFF_W0R 4194304L
#define OFF_WIH 8388608L
#define OFF_WHH 20971520L
#define OFF_WC1 33554432L
#define OFF_WC2 34603008L
__device__ __align__(16) __nv_bfloat16 g_wbf[35651584];

__device__ __forceinline__ float sigf(float x){ return 1.f/(1.f+expf(-x)); }

__device__ __forceinline__ unsigned long long pack2(float x, float y){
    unsigned long long r;
    asm("mov.b64 %0, {%1, %2};" : "=l"(r) : "f"(x), "f"(y));
    return r;
}
__device__ __forceinline__ void fma2(unsigned long long& d, unsigned long long a,
                                     unsigned long long b, unsigned long long c){
    asm("fma.rn.f32x2 %0, %1, %2, %3;" : "=l"(d) : "l"(a), "l"(b), "l"(c));
}
__device__ __forceinline__ float2 unpack2(unsigned long long v){
    float2 f;
    asm("mov.b64 {%0, %1}, %2;" : "=f"(f.x), "=f"(f.y) : "l"(v));
    return f;
}

__global__ void embed_k(const int* __restrict__ idx, const float* __restrict__ W,
                        float* __restrict__ out, int slen){
    int s = blockIdx.x, b = blockIdx.y;
    long tok = idx[b*slen + s];
    const float4* sp = (const float4*)(W + tok*1024);
    float4* dp = (float4*)(out + ((long)s*BA + b)*1024);
    for (int i = threadIdx.x; i < 256; i += blockDim.x) dp[i] = sp[i];
}

__global__ void dinit_k(float* __restrict__ dh, const float* __restrict__ h0,
                        float* __restrict__ dcc, const float* __restrict__ c0,
                        float* __restrict__ htl){
    int i = blockIdx.x*256 + threadIdx.x;
    dh[i] = h0[i];
    dcc[i] = c0[i];
    if (i < BA*HID) htl[i] = 0.f;
}

__global__ void cvt_k(__nv_bfloat16* __restrict__ dst, const float* __restrict__ src,
                      int srcld, int col0, int ncols, long total){
    long stride = (long)gridDim.x*blockDim.x;
    for (long i = (long)blockIdx.x*blockDim.x + threadIdx.x; i < total; i += stride){
        long r = i / ncols, cc = i - r*ncols;
        dst[i] = __float2bfloat16(src[r*srcld + col0 + cc]);
    }
}

// ---------------- big tiled GEMM with packed f32x2 FMA ----------------
// scat!=0: output row for local row m = (m&15)*TL + t0 + (m>>4)
__global__ __launch_bounds__(256) void gemm_k(
    const float* __restrict__ A, int lda,
    const float* __restrict__ B, int ldb, int transB,
    const float* __restrict__ b1, const float* __restrict__ b2,
    float* __restrict__ C, int ldc, int M, int N, int K, int scat, int t0)
{
    __shared__ float As[16][132];
    __shared__ float Bs[16][132];
    int m0 = blockIdx.y*128, n0 = blockIdx.x*128;
    int tid = threadIdx.x, tx = tid & 15, ty = tid >> 4;
    // acc2[i2][j]: rows (2*i2, 2*i2+1) of output col j (packed lo/hi)
    unsigned long long acc2[4][8];
#pragma unroll
    for (int i = 0; i < 4; i++)
#pragma unroll
        for (int j = 0; j < 8; j++) acc2[i][j] = 0ULL;

    for (int k0 = 0; k0 < K; k0 += 16) {
#pragma unroll
        for (int i = 0; i < 2; i++) {
            int e = tid + i*256, m = e >> 2, kq = e & 3;
            float4 v = make_float4(0,0,0,0);
            if (m0 + m < M) v = *(const float4*)(A + (long)(m0+m)*lda + k0 + kq*4);
            As[kq*4+0][m]=v.x; As[kq*4+1][m]=v.y; As[kq*4+2][m]=v.z; As[kq*4+3][m]=v.w;
        }
        if (transB) {
#pragma unroll
            for (int i = 0; i < 2; i++) {
                int e = tid + i*256, n = e >> 2, kq = e & 3;
                float4 v = *(const float4*)(B + (long)(n0+n)*ldb + k0 + kq*4);
                Bs[kq*4+0][n]=v.x; Bs[kq*4+1][n]=v.y; Bs[kq*4+2][n]=v.z; Bs[kq*4+3][n]=v.w;
            }
        } else {
#pragma unroll
            for (int i = 0; i < 2; i++) {
                int e = tid + i*256, kk = e >> 5, nq = e & 31;
                *(float4*)&Bs[kk][nq*4] = *(const float4*)(B + (long)(k0+kk)*ldb + n0 + nq*4);
            }
        }
        __syncthreads();
#pragma unroll
        for (int kk = 0; kk < 16; kk++) {
            // A row-pairs read directly as 64-bit lanes
            unsigned long long ap[4];
            {
                ulonglong2 u0 = *(const ulonglong2*)&As[kk][ty*8];
                ulonglong2 u1 = *(const ulonglong2*)&As[kk][ty*8+4];
                ap[0] = u0.x; ap[1] = u0.y; ap[2] = u1.x; ap[3] = u1.y;
            }
            float bv[8];
            *(float4*)&bv[0] = *(const float4*)&Bs[kk][tx*8];
            *(float4*)&bv[4] = *(const float4*)&Bs[kk][tx*8+4];
#pragma unroll
            for (int j = 0; j < 8; j++) {
                unsigned long long bb = pack2(bv[j], bv[j]);
#pragma unroll
                for (int i = 0; i < 4; i++)
                    fma2(acc2[i][j], ap[i], bb, acc2[i][j]);
            }
        }
        __syncthreads();
    }
#pragma unroll
    for (int i2 = 0; i2 < 4; i2++) {
        float lo[8], hi[8];
#pragma unroll
        for (int j = 0; j < 8; j++) {
            float2 f = unpack2(acc2[i2][j]);
            lo[j] = f.x; hi[j] = f.y;
        }
#pragma unroll
        for (int h = 0; h < 2; h++) {
            int m = m0 + ty*8 + 2*i2 + h;
            if (m < M) {
                long crow = scat ? ((long)(m & 15)*TL + t0 + (m >> 4)) : (long)m;
                float* Cr = C + crow*ldc + n0 + tx*8;
                const float* av = h ? hi : lo;
#pragma unroll
                for (int j = 0; j < 8; j++) {
                    int n = n0 + tx*8 + j;
                    float v = av[j];
                    if (b1) v += b1[n];
                    if (b2) v += b2[n];
                    Cr[j] = v;
                }
            }
        }
    }
}

// ------- fused encoder step: full-K matvec + LSTM cell, both dirs ----------
__global__ __launch_bounds__(256) void enc_fused_k(
    const float* __restrict__ Whh, const float* __restrict__ xg,
    const float* __restrict__ hin, float* __restrict__ hout,
    float* __restrict__ c, float* __restrict__ y,
    float* __restrict__ h0l, float* __restrict__ c0l, int step)
{
    __shared__ __align__(16) float hs[512][20];
    __shared__ float sg[64][17];
    int tid = threadIdx.x;
    int dir = blockIdx.x >> 5, hg = blockIdx.x & 31;
    int s = dir ? (SL-1-step) : step;
    int r = tid >> 2, q = tid & 3;
    float a0=0,a1=0,a2=0,a3=0;

    if (step > 0) {
        const float* hsrc = hin + dir*(BA*HD2);
#pragma unroll
        for (int i = 0; i < 32; i++) {
            int e = tid + i*256;
            hs[e & 511][e >> 9] = hsrc[e];
        }
        __syncthreads();
        int g = r >> 4, j = r & 15;
        const float* wr = Whh + ((long)dir*2048 + g*512 + hg*16 + j) * 512;
#pragma unroll 4
        for (int k = 0; k < 512; k += 8) {
            float w8[8];
            *(float4*)&w8[0] = *(const float4*)(wr + k);
            *(float4*)&w8[4] = *(const float4*)(wr + k + 4);
#pragma unroll
            for (int kk = 0; kk < 8; kk++) {
                float4 xv = *(const float4*)&hs[k+kk][q*4];
                a0 = fmaf(w8[kk], xv.x, a0);
                a1 = fmaf(w8[kk], xv.y, a1);
                a2 = fmaf(w8[kk], xv.z, a2);
                a3 = fmaf(w8[kk], xv.w, a3);
            }
        }
    }
    sg[r][q*4+0]=a0; sg[r][q*4+1]=a1; sg[r][q*4+2]=a2; sg[r][q*4+3]=a3;
    __syncthreads();

    int j = tid >> 4, b = tid & 15;
    int hd = hg*16 + j;
    long xb = ((long)s*BA + b)*4096 + dir*2048 + hd;
    float gi = sg[j     ][b] + xg[xb];
    float gf = sg[16 + j][b] + xg[xb + 512];
    float gg = sg[32 + j][b] + xg[xb + 1024];
    float go = sg[48 + j][b] + xg[xb + 1536];
    int ci = dir*(BA*HD2) + b*HD2 + hd;
    float cc = step ? c[ci] : 0.f;
    float cn = sigf(gf)*cc + sigf(gi)*tanhf(gg);
    float hn = sigf(go)*tanhf(cn);
    c[ci] = cn; hout[ci] = hn;
    y[((long)s*BA + b)*HID + dir*512 + hd] = hn;
    if (step == SL-1) {
        h0l[b*HID + dir*512 + hd] = hn;
        c0l[b*HID + dir*512 + hd] = cn;
    }
}

// -------- decoder matvec: single-shot front-batched loads, bf16 smem --------
__global__ __launch_bounds__(256) void mmbf_k(
    const __nv_bfloat16* __restrict__ W1, const __nv_bfloat16* __restrict__ W2,
    const float* __restrict__ x1, const float* __restrict__ x2,
    float* __restrict__ part, int rtot)
{
    __shared__ __align__(16) __nv_bfloat16 Wt[128][136];
    __shared__ __align__(16) float xs[128][20];
    int tid = threadIdx.x;
    int slice = blockIdx.x & 15, rg = blockIdx.x >> 4;
    int r0 = rg*128, k0 = slice*128;
    const __nv_bfloat16* W; const float* x; int ko;
    if (k0 < 1024) { W = W1; x = x1; ko = k0; }
    else           { W = W2; x = x2; ko = k0 - 1024; }

    uint4 wc[8];
    float xr[8];
#pragma unroll
    for (int i = 0; i < 8; i++) {
        int cidx = tid + i*256;
        int row = cidx >> 4, q = cidx & 15;
        wc[i] = *(const uint4*)(W + (long)(r0+row)*1024 + ko + q*8);
    }
#pragma unroll
    for (int i = 0; i < 8; i++) {
        int e = tid + i*256;
        int b = e >> 7, kk = e & 127;
        xr[i] = x[b*1024 + ko + kk];
    }
#pragma unroll
    for (int i = 0; i < 8; i++) {
        int cidx = tid + i*256;
        int row = cidx >> 4, q = cidx & 15;
        *(uint4*)&Wt[row][q*8] = wc[i];
    }
#pragma unroll
    for (int i = 0; i < 8; i++) {
        int e = tid + i*256;
        int b = e >> 7, kk = e & 127;
        xs[kk][b] = xr[i];
    }
    __syncthreads();

    int rp = tid >> 2, bq = tid & 3;
    float a00=0,a01=0,a02=0,a03=0,a10=0,a11=0,a12=0,a13=0;
#pragma unroll 8
    for (int k = 0; k < 128; k += 2) {
        __nv_bfloat162 wa = *(const __nv_bfloat162*)&Wt[2*rp  ][k];
        __nv_bfloat162 wb = *(const __nv_bfloat162*)&Wt[2*rp+1][k];
        float2 fa = __bfloat1622float2(wa);
        float2 fb = __bfloat1622float2(wb);
        float4 x0 = *(const float4*)&xs[k  ][4*bq];
        float4 x1v = *(const float4*)&xs[k+1][4*bq];
        a00 = fmaf(fa.x, x0.x, a00); a01 = fmaf(fa.x, x0.y, a01);
        a02 = fmaf(fa.x, x0.z, a02); a03 = fmaf(fa.x, x0.w, a03);
        a10 = fmaf(fb.x, x0.x, a10); a11 = fmaf(fb.x, x0.y, a11);
        a12 = fmaf(fb.x, x0.z, a12); a13 = fmaf(fb.x, x0.w, a13);
        a00 = fmaf(fa.y, x1v.x, a00); a01 = fmaf(fa.y, x1v.y, a01);
        a02 = fmaf(fa.y, x1v.z, a02); a03 = fmaf(fa.y, x1v.w, a03);
        a10 = fmaf(fb.y, x1v.x, a10); a11 = fmaf(fb.y, x1v.y, a11);
        a12 = fmaf(fb.y, x1v.z, a12); a13 = fmaf(fb.y, x1v.w, a13);
    }
    float* p = part + ((long)slice*rtot + r0 + 2*rp)*16 + 4*bq;
    *(float4*)p        = make_float4(a00,a01,a02,a03);
    *(float4*)(p + 16) = make_float4(a10,a11,a12,a13);
}

// ---------------- decoder cell ----------------
__global__ __launch_bounds__(256) void dec_cell_k(
    const float* __restrict__ part, const float* __restrict__ pre,
    const float* __restrict__ b1, const float* __restrict__ b2,
    float* __restrict__ c, float* __restrict__ hout)
{
    int idx = blockIdx.x*256 + threadIdx.x;
    int b = idx & 15, hd = idx >> 4;
    float g[4];
#pragma unroll
    for (int gi = 0; gi < 4; gi++) {
        int row = gi*HID + hd;
        float v;
        if (pre) v = pre[(long)b*4096 + row];
        else     v = b1[row] + b2[row];
#pragma unroll
        for (int sl = 0; sl < 16; sl++)
            v += part[((long)sl*4096 + row)*16 + b];
        g[gi] = v;
    }
    int ci = b*HID + hd;
    float cc = c[ci];
    float cn = sigf(g[1])*cc + sigf(g[0])*tanhf(g[2]);
    c[ci] = cn;
    hout[ci] = sigf(g[3])*tanhf(cn);
}

// ---------------- h_tilde cell ----------------
__global__ __launch_bounds__(256) void htanh_k(
    const float* __restrict__ part, const float* __restrict__ bc,
    float* __restrict__ htl, float* __restrict__ hbt, int t)
{
    int idx = blockIdx.x*256 + threadIdx.x;
    int b = idx & 15, hd = idx >> 4;
    float v = bc[hd];
#pragma unroll
    for (int sl = 0; sl < 16; sl++)
        v += part[((long)sl*1024 + hd)*16 + b];
    float h = tanhf(v);
    htl[b*HID + hd] = h;
    hbt[((long)t*BA + b)*HID + hd] = h;
}

// ---------------- attention ----------------
__global__ __launch_bounds__(256) void attn_k(
    const float* __restrict__ h3, const float* __restrict__ hA,
    const float* __restrict__ hsrc, float* __restrict__ ctx)
{
    __shared__ float h3s[HID];
    __shared__ float sc[SL];
    int b = blockIdx.x, tid = threadIdx.x;
    for (int i = tid; i < HID; i += 256) h3s[i] = h3[b*HID + i];
    __syncthreads();
    int w = tid >> 5, lane = tid & 31;
    for (int s = w; s < SL; s += 8) {
        const float* hp = hA + ((long)s*BA + b)*HID;
        float p = 0.f;
        for (int k = lane; k < HID; k += 32) p = fmaf(h3s[k], hp[k], p);
#pragma unroll
        for (int o = 16; o > 0; o >>= 1) p += __shfl_xor_sync(0xffffffffu, p, o);
        if (lane == 0) sc[s] = p;
    }
    __syncthreads();
    if (tid == 0) {
        float mx = sc[0];
        for (int s = 1; s < SL; s++) mx = fmaxf(mx, sc[s]);
        float sum = 0.f;
        for (int s = 0; s < SL; s++) { sc[s] = expf(sc[s]-mx); sum += sc[s]; }
        float inv = 1.f/sum;
        for (int s = 0; s < SL; s++) sc[s] *= inv;
    }
    __syncthreads();
    float4 acc = make_float4(0,0,0,0);
    int k = tid*4;
    for (int s = 0; s < SL; s++) {
        float ws = sc[s];
        float4 v = *(const float4*)(hsrc + ((long)s*BA + b)*HID + k);
        acc.x = fmaf(ws, v.x, acc.x); acc.y = fmaf(ws, v.y, acc.y);
        acc.z = fmaf(ws, v.z, acc.z); acc.w = fmaf(ws, v.w, acc.w);
    }
    *(float4*)(ctx + b*HID + k) = acc;
}

// ---------------- log-softmax ----------------
__global__ __launch_bounds__(256) void lsm_k(float* __restrict__ out)
{
    __shared__ float red[256];
    long m = blockIdx.x;
    float* row = out + m*VOUT;
    int tid = threadIdx.x;
    float mx = -1e30f;
    for (int i = tid; i < VOUT/4; i += 256) {
        float4 v = *(const float4*)(row + i*4);
        mx = fmaxf(mx, fmaxf(fmaxf(v.x, v.y), fmaxf(v.z, v.w)));
    }
    red[tid] = mx; __syncthreads();
    for (int o = 128; o > 0; o >>= 1) { if (tid < o) red[tid] = fmaxf(red[tid], red[tid+o]); __syncthreads(); }
    mx = red[0]; __syncthreads();
    float sum = 0.f;
    for (int i = tid; i < VOUT/4; i += 256) {
        float4 v = *(const float4*)(row + i*4);
        sum += expf(v.x-mx)+expf(v.y-mx)+expf(v.z-mx)+expf(v.w-mx);
    }
    red[tid] = sum; __syncthreads();
    for (int o = 128; o > 0; o >>= 1) { if (tid < o) red[tid] += red[tid+o]; __syncthreads(); }
    float lse = mx + logf(red[0]);
    for (int i = tid; i < VOUT/4; i += 256) {
        float4 v = *(const float4*)(row + i*4);
        v.x -= lse; v.y -= lse; v.z -= lse; v.w -= lse;
        *(float4*)(row + i*4) = v;
    }
}

static float* sym(const void* s){ void* p = nullptr; cudaGetSymbolAddress(&p, s); return (float*)p; }

extern "C" void kernel_launch(void* const* d_in, const int* in_sizes, int n_in,
                              void* d_out, int out_size)
{
    const int*   src   = (const int*)  d_in[0];
    const int*   tgt   = (const int*)  d_in[1];
    const float* embS  = (const float*)d_in[2];
    const float* embD  = (const float*)d_in[3];
    const float* eWih  = (const float*)d_in[4];
    const float* eWhh  = (const float*)d_in[5];
    const float* ebih  = (const float*)d_in[6];
    const float* ebhh  = (const float*)d_in[7];
    const float* d0Wih = (const float*)d_in[8];
    const float* d0Whh = (const float*)d_in[9];
    const float* d0bih = (const float*)d_in[10];
    const float* d0bhh = (const float*)d_in[11];
    const float* dWih  = (const float*)d_in[12];
    const float* dWhh  = (const float*)d_in[13];
    const float* dbih  = (const float*)d_in[14];
    const float* dbhh  = (const float*)d_in[15];
    const float* Wattn = (const float*)d_in[16];
    const float* Wcat  = (const float*)d_in[17];
    const float* bcat  = (const float*)d_in[18];
    const float* Wout  = (const float*)d_in[19];
    const float* bout  = (const float*)d_in[20];
    float* out = (float*)d_out;

    float* encx = sym(g_encx);  float* ency = sym(g_ency);
    float* encxg = sym(g_encxg);
    float* ehA = sym(g_enchA);  float* ehB = sym(g_enchB);
    float* ecc = sym(g_encc);
    float* h0 = sym(g_h0);      float* c0 = sym(g_c0);
    float* demb = sym(g_demb);  float* pre0 = sym(g_pre0);
    float* dhA = sym(g_dhA);    float* dhB = sym(g_dhB);
    float* dc  = sym(g_dc);
    float* htl = sym(g_htl);    float* ctx = sym(g_ctx);
    float* hAp = sym(g_hA);     float* hbt = sym(g_hbt);
    float* part = sym(g_part);
    __nv_bfloat16* wbf = (__nv_bfloat16*)sym(g_wbf);

    // ---- bf16 weight conversion (decoder recurrent path) ----
    {
        long n1 = 4194304L, n3 = 12582912L, nc = 1048576L;
        cvt_k<<<1024, 256>>>(wbf + OFF_W0H, d0Wih, 2048, 1024, 1024, n1);
        cvt_k<<<1024, 256>>>(wbf + OFF_W0R, d0Whh, 1024, 0, 1024, n1);
        cvt_k<<<1024, 256>>>(wbf + OFF_WIH, dWih, 1024, 0, 1024, n3);
        cvt_k<<<1024, 256>>>(wbf + OFF_WHH, dWhh, 1024, 0, 1024, n3);
        cvt_k<<<1024, 256>>>(wbf + OFF_WC1, Wcat, 2048, 0, 1024, nc);
        cvt_k<<<1024, 256>>>(wbf + OFF_WC2, Wcat, 2048, 1024, 1024, nc);
    }

    // ---- encoder ----
    embed_k<<<dim3(SL, BA), 256>>>(src, embS, encx, SL);
    float* xin = encx; float* yout = ency;
    for (int l = 0; l < NL; l++) {
        gemm_k<<<dim3(32, 7), 256>>>(xin, HID, eWih + (long)l*4096*1024, 1024, 1,
                                     ebih + l*4096, ebhh + l*4096, encxg, 4096,
                                     SL*BA, 4096, 1024, 0, 0);
        float* hi = ehA; float* ho = ehB;
        const float* Whh = eWhh + (long)l*4096*512;
        for (int st = 0; st < SL; st++) {
            enc_fused_k<<<64, 256>>>(Whh, encxg, hi, ho, ecc, yout,
                                     h0 + (long)l*BA*HID, c0 + (long)l*BA*HID, st);
            float* tmp = hi; hi = ho; ho = tmp;
        }
        float* t = xin; xin = yout; yout = t;
    }
    float* hsrc = xin;

    // ---- decoder precompute ----
    embed_k<<<dim3(TL, BA), 256>>>(tgt, embD, demb, TL);
    gemm_k<<<dim3(32, 7), 256>>>(demb, HID, d0Wih, 2048, 1, d0bih, d0bhh,
                                 pre0, 4096, TL*BA, 4096, 1024, 0, 0);
    gemm_k<<<dim3(8, 7), 256>>>(hsrc, HID, Wattn, 1024, 0, nullptr, nullptr,
                                hAp, HID, SL*BA, 1024, 1024, 0, 0);
    dinit_k<<<NL*BA*HID/256, 256>>>(dhA, h0, dc, c0, htl);

    // ---- decoder loop ----
    float* hi = dhA; float* ho = dhB;
    for (int t = 0; t < TL; t++) {
        mmbf_k<<<512, 256>>>(wbf + OFF_W0H, wbf + OFF_W0R, htl, hi, part, 4096);
        dec_cell_k<<<64, 256>>>(part, pre0 + (long)t*BA*4096, nullptr, nullptr,
                                dc, ho);
        for (int i = 0; i < NL-1; i++) {
            mmbf_k<<<512, 256>>>(wbf + OFF_WIH + (long)i*4194304,
                                 wbf + OFF_WHH + (long)i*4194304,
                                 ho + (long)i*BA*HID,
                                 hi + (long)(i+1)*BA*HID, part, 4096);
            dec_cell_k<<<64, 256>>>(part, nullptr, dbih + i*4096, dbhh + i*4096,
                                    dc + (long)(i+1)*BA*HID, ho + (long)(i+1)*BA*HID);
        }
        attn_k<<<BA, 256>>>(ho + (long)3*BA*HID, hAp, hsrc, ctx);
        mmbf_k<<<128, 256>>>(wbf + OFF_WC1, wbf + OFF_WC2,
                             ho + (long)3*BA*HID, ctx, part, 1024);
        htanh_k<<<64, 256>>>(part, bcat, htl, hbt, t);
        float* tmp = hi; hi = ho; ho = tmp;
    }

    // ---- generator ----
    gemm_k<<<dim3(250, 7), 256>>>(hbt, HID, Wout, 1024, 1, bout, nullptr,
                                  out, VOUT, TL*BA, VOUT, 1024, 1, 0);
    lsm_k<<<TL*BA, 256>>>(out);
}

// round 10
// speedup vs baseline: 1.2338x; 1.2338x over previous
#include <cuda_runtime.h>
#include <cuda_bf16.h>
#include <math.h>

#define SL 50
#define TL 50
#define BA 16
#define HID 1024
#define HD2 512
#define NL 4
#define VOUT 32000

__device__ __align__(16) float g_encx [SL*BA*HID];
__device__ __align__(16) float g_ency [SL*BA*HID];
__device__ __align__(16) float g_encxg[SL*BA*4096];
__device__ __align__(16) float g_enchA[2*BA*HD2];
__device__ __align__(16) float g_enchB[2*BA*HD2];
__device__ __align__(16) float g_encc [2*BA*HD2];
__device__ __align__(16) float g_h0   [NL*BA*HID];
__device__ __align__(16) float g_c0   [NL*BA*HID];
__device__ __align__(16) float g_demb [TL*BA*HID];
__device__ __align__(16) float g_pre0 [TL*BA*4096];
__device__ __align__(16) float g_dhA  [NL*BA*HID];
__device__ __align__(16) float g_dhB  [NL*BA*HID];
__device__ __align__(16) float g_dc   [NL*BA*HID];
__device__ __align__(16) float g_htl  [BA*HID];
__device__ __align__(16) float g_ctx  [BA*HID];
__device__ __align__(16) float g_hA   [SL*BA*HID];
__device__ __align__(16) float g_hbt  [TL*BA*HID];   // [t][b][H]
__device__ __align__(16) float g_part [16*4096*16];
#define OFF_W0H 0L
#define OFF_W0R 4194304L
#define OFF_WIH 8388608L
#define OFF_WHH 20971520L
#define OFF_WC1 33554432L
#define OFF_WC2 34603008L
__device__ __align__(16) __nv_bfloat16 g_wbf[35651584];

__device__ __forceinline__ float sigf(float x){ return 1.f/(1.f+expf(-x)); }

__device__ __forceinline__ unsigned cvt_tf32(float f){
    unsigned u;
    asm("cvt.rna.tf32.f32 %0, %1;" : "=r"(u) : "f"(f));
    return u;
}

__global__ void embed_k(const int* __restrict__ idx, const float* __restrict__ W,
                        float* __restrict__ out, int slen){
    int s = blockIdx.x, b = blockIdx.y;
    long tok = idx[b*slen + s];
    const float4* sp = (const float4*)(W + tok*1024);
    float4* dp = (float4*)(out + ((long)s*BA + b)*1024);
    for (int i = threadIdx.x; i < 256; i += blockDim.x) dp[i] = sp[i];
}

__global__ void dinit_k(float* __restrict__ dh, const float* __restrict__ h0,
                        float* __restrict__ dcc, const float* __restrict__ c0,
                        float* __restrict__ htl){
    int i = blockIdx.x*256 + threadIdx.x;
    dh[i] = h0[i];
    dcc[i] = c0[i];
    if (i < BA*HID) htl[i] = 0.f;
}

__global__ void cvt_k(__nv_bfloat16* __restrict__ dst, const float* __restrict__ src,
                      int srcld, int col0, int ncols, long total){
    long stride = (long)gridDim.x*blockDim.x;
    for (long i = (long)blockIdx.x*blockDim.x + threadIdx.x; i < total; i += stride){
        long r = i / ncols, cc = i - r*ncols;
        dst[i] = __float2bfloat16(src[r*srcld + col0 + cc]);
    }
}

// ---------- tf32 tensor-core GEMM: C = A[M,K] @ B[N,K]^T (+b1 +b2) ----------
// grid (N/128, ceil(M/128)), 256 threads = 8 warps (2m x 4n), warp tile 64x32.
// scat!=0: output row for local row m = (m&15)*TL + t0 + (m>>4)
__global__ __launch_bounds__(256) void gemm_tc_k(
    const float* __restrict__ A, int lda,
    const float* __restrict__ B, int ldb,
    const float* __restrict__ b1, const float* __restrict__ b2,
    float* __restrict__ C, int ldc, int M, int N, int K, int scat, int t0)
{
    __shared__ unsigned As[128][36];
    __shared__ unsigned Bs[128][36];
    int tid = threadIdx.x;
    int m0 = blockIdx.y*128, n0 = blockIdx.x*128;
    int warp = tid >> 5, lane = tid & 31;
    int wm = warp >> 2, wn = warp & 3;
    int g = lane >> 2, tg = lane & 3;
    float acc[4][4][4];
#pragma unroll
    for (int mt = 0; mt < 4; mt++)
#pragma unroll
        for (int nt = 0; nt < 4; nt++)
#pragma unroll
            for (int i = 0; i < 4; i++) acc[mt][nt][i] = 0.f;

    for (int k0 = 0; k0 < K; k0 += 32) {
#pragma unroll
        for (int i = 0; i < 4; i++) {
            int e = tid + i*256;
            int m = e >> 3, kq = e & 7;
            float4 v = make_float4(0,0,0,0);
            if (m0 + m < M) v = *(const float4*)(A + (long)(m0+m)*lda + k0 + kq*4);
            unsigned* d = &As[m][kq*4];
            d[0]=cvt_tf32(v.x); d[1]=cvt_tf32(v.y); d[2]=cvt_tf32(v.z); d[3]=cvt_tf32(v.w);
        }
#pragma unroll
        for (int i = 0; i < 4; i++) {
            int e = tid + i*256;
            int n = e >> 3, kq = e & 7;
            float4 v = *(const float4*)(B + (long)(n0+n)*ldb + k0 + kq*4);
            unsigned* d = &Bs[n][kq*4];
            d[0]=cvt_tf32(v.x); d[1]=cvt_tf32(v.y); d[2]=cvt_tf32(v.z); d[3]=cvt_tf32(v.w);
        }
        __syncthreads();
#pragma unroll
        for (int ks = 0; ks < 4; ks++) {
            int kb = ks*8;
            unsigned a[4][4], b[4][2];
#pragma unroll
            for (int mt = 0; mt < 4; mt++) {
                int mb = wm*64 + mt*16;
                a[mt][0] = As[mb+g  ][kb+tg];
                a[mt][1] = As[mb+g+8][kb+tg];
                a[mt][2] = As[mb+g  ][kb+tg+4];
                a[mt][3] = As[mb+g+8][kb+tg+4];
            }
#pragma unroll
            for (int nt = 0; nt < 4; nt++) {
                int nb = wn*32 + nt*8;
                b[nt][0] = Bs[nb+g][kb+tg];
                b[nt][1] = Bs[nb+g][kb+tg+4];
            }
#pragma unroll
            for (int mt = 0; mt < 4; mt++)
#pragma unroll
                for (int nt = 0; nt < 4; nt++)
                    asm volatile(
                        "mma.sync.aligned.m16n8k8.row.col.f32.tf32.tf32.f32 "
                        "{%0,%1,%2,%3}, {%4,%5,%6,%7}, {%8,%9}, {%0,%1,%2,%3};"
                        : "+f"(acc[mt][nt][0]), "+f"(acc[mt][nt][1]),
                          "+f"(acc[mt][nt][2]), "+f"(acc[mt][nt][3])
                        : "r"(a[mt][0]), "r"(a[mt][1]), "r"(a[mt][2]), "r"(a[mt][3]),
                          "r"(b[nt][0]), "r"(b[nt][1]));
        }
        __syncthreads();
    }
#pragma unroll
    for (int mt = 0; mt < 4; mt++) {
#pragma unroll
        for (int h = 0; h < 2; h++) {
            int m = m0 + wm*64 + mt*16 + g + h*8;
            if (m < M) {
                long crow = scat ? ((long)(m & 15)*TL + t0 + (m >> 4)) : (long)m;
#pragma unroll
                for (int nt = 0; nt < 4; nt++) {
                    int n = n0 + wn*32 + nt*8 + tg*2;
                    float v0 = acc[mt][nt][h*2+0];
                    float v1 = acc[mt][nt][h*2+1];
                    if (b1) { v0 += b1[n]; v1 += b1[n+1]; }
                    if (b2) { v0 += b2[n]; v1 += b2[n+1]; }
                    C[crow*ldc + n]     = v0;
                    C[crow*ldc + n + 1] = v1;
                }
            }
        }
    }
}

// ---------------- scalar fp32 GEMM (kept for the small transB=0 hA) ---------
__global__ __launch_bounds__(256) void gemm_k(
    const float* __restrict__ A, int lda,
    const float* __restrict__ B, int ldb, int transB,
    const float* __restrict__ b1, const float* __restrict__ b2,
    float* __restrict__ C, int ldc, int M, int N, int K, int scat, int t0)
{
    __shared__ float As[16][132];
    __shared__ float Bs[16][132];
    int m0 = blockIdx.y*128, n0 = blockIdx.x*128;
    int tid = threadIdx.x, tx = tid & 15, ty = tid >> 4;
    float acc[8][8];
#pragma unroll
    for (int i = 0; i < 8; i++)
#pragma unroll
        for (int j = 0; j < 8; j++) acc[i][j] = 0.f;

    for (int k0 = 0; k0 < K; k0 += 16) {
#pragma unroll
        for (int i = 0; i < 2; i++) {
            int e = tid + i*256, m = e >> 2, kq = e & 3;
            float4 v = make_float4(0,0,0,0);
            if (m0 + m < M) v = *(const float4*)(A + (long)(m0+m)*lda + k0 + kq*4);
            As[kq*4+0][m]=v.x; As[kq*4+1][m]=v.y; As[kq*4+2][m]=v.z; As[kq*4+3][m]=v.w;
        }
        if (transB) {
#pragma unroll
            for (int i = 0; i < 2; i++) {
                int e = tid + i*256, n = e >> 2, kq = e & 3;
                float4 v = *(const float4*)(B + (long)(n0+n)*ldb + k0 + kq*4);
                Bs[kq*4+0][n]=v.x; Bs[kq*4+1][n]=v.y; Bs[kq*4+2][n]=v.z; Bs[kq*4+3][n]=v.w;
            }
        } else {
#pragma unroll
            for (int i = 0; i < 2; i++) {
                int e = tid + i*256, kk = e >> 5, nq = e & 31;
                *(float4*)&Bs[kk][nq*4] = *(const float4*)(B + (long)(k0+kk)*ldb + n0 + nq*4);
            }
        }
        __syncthreads();
#pragma unroll
        for (int kk = 0; kk < 16; kk++) {
            float a[8], bv[8];
            *(float4*)&a[0] = *(float4*)&As[kk][ty*8];
            *(float4*)&a[4] = *(float4*)&As[kk][ty*8+4];
            *(float4*)&bv[0] = *(float4*)&Bs[kk][tx*8];
            *(float4*)&bv[4] = *(float4*)&Bs[kk][tx*8+4];
#pragma unroll
            for (int i = 0; i < 8; i++)
#pragma unroll
                for (int j = 0; j < 8; j++) acc[i][j] = fmaf(a[i], bv[j], acc[i][j]);
        }
        __syncthreads();
    }
#pragma unroll
    for (int i = 0; i < 8; i++) {
        int m = m0 + ty*8 + i;
        if (m < M) {
            long crow = scat ? ((long)(m & 15)*TL + t0 + (m >> 4)) : (long)m;
            float* Cr = C + crow*ldc + n0 + tx*8;
#pragma unroll
            for (int j = 0; j < 8; j++) {
                int n = n0 + tx*8 + j;
                float v = acc[i][j];
                if (b1) v += b1[n];
                if (b2) v += b2[n];
                Cr[j] = v;
            }
        }
    }
}

// ------- fused encoder step: full-K matvec + LSTM cell, both dirs ----------
__global__ __launch_bounds__(256) void enc_fused_k(
    const float* __restrict__ Whh, const float* __restrict__ xg,
    const float* __restrict__ hin, float* __restrict__ hout,
    float* __restrict__ c, float* __restrict__ y,
    float* __restrict__ h0l, float* __restrict__ c0l, int step)
{
    __shared__ __align__(16) float hs[512][20];
    __shared__ float sg[64][17];
    int tid = threadIdx.x;
    int dir = blockIdx.x >> 5, hg = blockIdx.x & 31;
    int s = dir ? (SL-1-step) : step;
    int r = tid >> 2, q = tid & 3;
    float a0=0,a1=0,a2=0,a3=0;

    if (step > 0) {
        const float* hsrc = hin + dir*(BA*HD2);
#pragma unroll
        for (int i = 0; i < 32; i++) {
            int e = tid + i*256;
            hs[e & 511][e >> 9] = hsrc[e];
        }
        __syncthreads();
        int g = r >> 4, j = r & 15;
        const float* wr = Whh + ((long)dir*2048 + g*512 + hg*16 + j) * 512;
#pragma unroll 4
        for (int k = 0; k < 512; k += 8) {
            float w8[8];
            *(float4*)&w8[0] = *(const float4*)(wr + k);
            *(float4*)&w8[4] = *(const float4*)(wr + k + 4);
#pragma unroll
            for (int kk = 0; kk < 8; kk++) {
                float4 xv = *(const float4*)&hs[k+kk][q*4];
                a0 = fmaf(w8[kk], xv.x, a0);
                a1 = fmaf(w8[kk], xv.y, a1);
                a2 = fmaf(w8[kk], xv.z, a2);
                a3 = fmaf(w8[kk], xv.w, a3);
            }
        }
    }
    sg[r][q*4+0]=a0; sg[r][q*4+1]=a1; sg[r][q*4+2]=a2; sg[r][q*4+3]=a3;
    __syncthreads();

    int j = tid >> 4, b = tid & 15;
    int hd = hg*16 + j;
    long xb = ((long)s*BA + b)*4096 + dir*2048 + hd;
    float gi = sg[j     ][b] + xg[xb];
    float gf = sg[16 + j][b] + xg[xb + 512];
    float gg = sg[32 + j][b] + xg[xb + 1024];
    float go = sg[48 + j][b] + xg[xb + 1536];
    int ci = dir*(BA*HD2) + b*HD2 + hd;
    float cc = step ? c[ci] : 0.f;
    float cn = sigf(gf)*cc + sigf(gi)*tanhf(gg);
    float hn = sigf(go)*tanhf(cn);
    c[ci] = cn; hout[ci] = hn;
    y[((long)s*BA + b)*HID + dir*512 + hd] = hn;
    if (step == SL-1) {
        h0l[b*HID + dir*512 + hd] = hn;
        c0l[b*HID + dir*512 + hd] = cn;
    }
}

// -------- decoder matvec: single-shot front-batched loads, bf16 smem --------
__global__ __launch_bounds__(256) void mmbf_k(
    const __nv_bfloat16* __restrict__ W1, const __nv_bfloat16* __restrict__ W2,
    const float* __restrict__ x1, const float* __restrict__ x2,
    float* __restrict__ part, int rtot)
{
    __shared__ __align__(16) __nv_bfloat16 Wt[128][136];
    __shared__ __align__(16) float xs[128][20];
    int tid = threadIdx.x;
    int slice = blockIdx.x & 15, rg = blockIdx.x >> 4;
    int r0 = rg*128, k0 = slice*128;
    const __nv_bfloat16* W; const float* x; int ko;
    if (k0 < 1024) { W = W1; x = x1; ko = k0; }
    else           { W = W2; x = x2; ko = k0 - 1024; }

    uint4 wc[8];
    float xr[8];
#pragma unroll
    for (int i = 0; i < 8; i++) {
        int cidx = tid + i*256;
        int row = cidx >> 4, q = cidx & 15;
        wc[i] = *(const uint4*)(W + (long)(r0+row)*1024 + ko + q*8);
    }
#pragma unroll
    for (int i = 0; i < 8; i++) {
        int e = tid + i*256;
        int b = e >> 7, kk = e & 127;
        xr[i] = x[b*1024 + ko + kk];
    }
#pragma unroll
    for (int i = 0; i < 8; i++) {
        int cidx = tid + i*256;
        int row = cidx >> 4, q = cidx & 15;
        *(uint4*)&Wt[row][q*8] = wc[i];
    }
#pragma unroll
    for (int i = 0; i < 8; i++) {
        int e = tid + i*256;
        int b = e >> 7, kk = e & 127;
        xs[kk][b] = xr[i];
    }
    __syncthreads();

    int rp = tid >> 2, bq = tid & 3;
    float a00=0,a01=0,a02=0,a03=0,a10=0,a11=0,a12=0,a13=0;
#pragma unroll 8
    for (int k = 0; k < 128; k += 2) {
        __nv_bfloat162 wa = *(const __nv_bfloat162*)&Wt[2*rp  ][k];
        __nv_bfloat162 wb = *(const __nv_bfloat162*)&Wt[2*rp+1][k];
        float2 fa = __bfloat1622float2(wa);
        float2 fb = __bfloat1622float2(wb);
        float4 x0 = *(const float4*)&xs[k  ][4*bq];
        float4 x1v = *(const float4*)&xs[k+1][4*bq];
        a00 = fmaf(fa.x, x0.x, a00); a01 = fmaf(fa.x, x0.y, a01);
        a02 = fmaf(fa.x, x0.z, a02); a03 = fmaf(fa.x, x0.w, a03);
        a10 = fmaf(fb.x, x0.x, a10); a11 = fmaf(fb.x, x0.y, a11);
        a12 = fmaf(fb.x, x0.z, a12); a13 = fmaf(fb.x, x0.w, a13);
        a00 = fmaf(fa.y, x1v.x, a00); a01 = fmaf(fa.y, x1v.y, a01);
        a02 = fmaf(fa.y, x1v.z, a02); a03 = fmaf(fa.y, x1v.w, a03);
        a10 = fmaf(fb.y, x1v.x, a10); a11 = fmaf(fb.y, x1v.y, a11);
        a12 = fmaf(fb.y, x1v.z, a12); a13 = fmaf(fb.y, x1v.w, a13);
    }
    float* p = part + ((long)slice*rtot + r0 + 2*rp)*16 + 4*bq;
    *(float4*)p        = make_float4(a00,a01,a02,a03);
    *(float4*)(p + 16) = make_float4(a10,a11,a12,a13);
}

// ---------------- decoder cell ----------------
__global__ __launch_bounds__(256) void dec_cell_k(
    const float* __restrict__ part, const float* __restrict__ pre,
    const float* __restrict__ b1, const float* __restrict__ b2,
    float* __restrict__ c, float* __restrict__ hout)
{
    int idx = blockIdx.x*256 + threadIdx.x;
    int b = idx & 15, hd = idx >> 4;
    float g[4];
#pragma unroll
    for (int gi = 0; gi < 4; gi++) {
        int row = gi*HID + hd;
        float v;
        if (pre) v = pre[(long)b*4096 + row];
        else     v = b1[row] + b2[row];
#pragma unroll
        for (int sl = 0; sl < 16; sl++)
            v += part[((long)sl*4096 + row)*16 + b];
        g[gi] = v;
    }
    int ci = b*HID + hd;
    float cc = c[ci];
    float cn = sigf(g[1])*cc + sigf(g[0])*tanhf(g[2]);
    c[ci] = cn;
    hout[ci] = sigf(g[3])*tanhf(cn);
}

// ---------------- h_tilde cell ----------------
__global__ __launch_bounds__(256) void htanh_k(
    const float* __restrict__ part, const float* __restrict__ bc,
    float* __restrict__ htl, float* __restrict__ hbt, int t)
{
    int idx = blockIdx.x*256 + threadIdx.x;
    int b = idx & 15, hd = idx >> 4;
    float v = bc[hd];
#pragma unroll
    for (int sl = 0; sl < 16; sl++)
        v += part[((long)sl*1024 + hd)*16 + b];
    float h = tanhf(v);
    htl[b*HID + hd] = h;
    hbt[((long)t*BA + b)*HID + hd] = h;
}

// ---------------- attention ----------------
__global__ __launch_bounds__(256) void attn_k(
    const float* __restrict__ h3, const float* __restrict__ hA,
    const float* __restrict__ hsrc, float* __restrict__ ctx)
{
    __shared__ float h3s[HID];
    __shared__ float sc[SL];
    int b = blockIdx.x, tid = threadIdx.x;
    for (int i = tid; i < HID; i += 256) h3s[i] = h3[b*HID + i];
    __syncthreads();
    int w = tid >> 5, lane = tid & 31;
    for (int s = w; s < SL; s += 8) {
        const float* hp = hA + ((long)s*BA + b)*HID;
        float p = 0.f;
        for (int k = lane; k < HID; k += 32) p = fmaf(h3s[k], hp[k], p);
#pragma unroll
        for (int o = 16; o > 0; o >>= 1) p += __shfl_xor_sync(0xffffffffu, p, o);
        if (lane == 0) sc[s] = p;
    }
    __syncthreads();
    if (tid == 0) {
        float mx = sc[0];
        for (int s = 1; s < SL; s++) mx = fmaxf(mx, sc[s]);
        float sum = 0.f;
        for (int s = 0; s < SL; s++) { sc[s] = expf(sc[s]-mx); sum += sc[s]; }
        float inv = 1.f/sum;
        for (int s = 0; s < SL; s++) sc[s] *= inv;
    }
    __syncthreads();
    float4 acc = make_float4(0,0,0,0);
    int k = tid*4;
    for (int s = 0; s < SL; s++) {
        float ws = sc[s];
        float4 v = *(const float4*)(hsrc + ((long)s*BA + b)*HID + k);
        acc.x = fmaf(ws, v.x, acc.x); acc.y = fmaf(ws, v.y, acc.y);
        acc.z = fmaf(ws, v.z, acc.z); acc.w = fmaf(ws, v.w, acc.w);
    }
    *(float4*)(ctx + b*HID + k) = acc;
}

// ---------------- log-softmax ----------------
__global__ __launch_bounds__(256) void lsm_k(float* __restrict__ out)
{
    __shared__ float red[256];
    long m = blockIdx.x;
    float* row = out + m*VOUT;
    int tid = threadIdx.x;
    float mx = -1e30f;
    for (int i = tid; i < VOUT/4; i += 256) {
        float4 v = *(const float4*)(row + i*4);
        mx = fmaxf(mx, fmaxf(fmaxf(v.x, v.y), fmaxf(v.z, v.w)));
    }
    red[tid] = mx; __syncthreads();
    for (int o = 128; o > 0; o >>= 1) { if (tid < o) red[tid] = fmaxf(red[tid], red[tid+o]); __syncthreads(); }
    mx = red[0]; __syncthreads();
    float sum = 0.f;
    for (int i = tid; i < VOUT/4; i += 256) {
        float4 v = *(const float4*)(row + i*4);
        sum += expf(v.x-mx)+expf(v.y-mx)+expf(v.z-mx)+expf(v.w-mx);
    }
    red[tid] = sum; __syncthreads();
    for (int o = 128; o > 0; o >>= 1) { if (tid < o) red[tid] += red[tid+o]; __syncthreads(); }
    float lse = mx + logf(red[0]);
    for (int i = tid; i < VOUT/4; i += 256) {
        float4 v = *(const float4*)(row + i*4);
        v.x -= lse; v.y -= lse; v.z -= lse; v.w -= lse;
        *(float4*)(row + i*4) = v;
    }
}

static float* sym(const void* s){ void* p = nullptr; cudaGetSymbolAddress(&p, s); return (float*)p; }

extern "C" void kernel_launch(void* const* d_in, const int* in_sizes, int n_in,
                              void* d_out, int out_size)
{
    const int*   src   = (const int*)  d_in[0];
    const int*   tgt   = (const int*)  d_in[1];
    const float* embS  = (const float*)d_in[2];
    const float* embD  = (const float*)d_in[3];
    const float* eWih  = (const float*)d_in[4];
    const float* eWhh  = (const float*)d_in[5];
    const float* ebih  = (const float*)d_in[6];
    const float* ebhh  = (const float*)d_in[7];
    const float* d0Wih = (const float*)d_in[8];
    const float* d0Whh = (const float*)d_in[9];
    const float* d0bih = (const float*)d_in[10];
    const float* d0bhh = (const float*)d_in[11];
    const float* dWih  = (const float*)d_in[12];
    const float* dWhh  = (const float*)d_in[13];
    const float* dbih  = (const float*)d_in[14];
    const float* dbhh  = (const float*)d_in[15];
    const float* Wattn = (const float*)d_in[16];
    const float* Wcat  = (const float*)d_in[17];
    const float* bcat  = (const float*)d_in[18];
    const float* Wout  = (const float*)d_in[19];
    const float* bout  = (const float*)d_in[20];
    float* out = (float*)d_out;

    float* encx = sym(g_encx);  float* ency = sym(g_ency);
    float* encxg = sym(g_encxg);
    float* ehA = sym(g_enchA);  float* ehB = sym(g_enchB);
    float* ecc = sym(g_encc);
    float* h0 = sym(g_h0);      float* c0 = sym(g_c0);
    float* demb = sym(g_demb);  float* pre0 = sym(g_pre0);
    float* dhA = sym(g_dhA);    float* dhB = sym(g_dhB);
    float* dc  = sym(g_dc);
    float* htl = sym(g_htl);    float* ctx = sym(g_ctx);
    float* hAp = sym(g_hA);     float* hbt = sym(g_hbt);
    float* part = sym(g_part);
    __nv_bfloat16* wbf = (__nv_bfloat16*)sym(g_wbf);

    // ---- bf16 weight conversion (decoder recurrent path) ----
    {
        long n1 = 4194304L, n3 = 12582912L, nc = 1048576L;
        cvt_k<<<1024, 256>>>(wbf + OFF_W0H, d0Wih, 2048, 1024, 1024, n1);
        cvt_k<<<1024, 256>>>(wbf + OFF_W0R, d0Whh, 1024, 0, 1024, n1);
        cvt_k<<<1024, 256>>>(wbf + OFF_WIH, dWih, 1024, 0, 1024, n3);
        cvt_k<<<1024, 256>>>(wbf + OFF_WHH, dWhh, 1024, 0, 1024, n3);
        cvt_k<<<1024, 256>>>(wbf + OFF_WC1, Wcat, 2048, 0, 1024, nc);
        cvt_k<<<1024, 256>>>(wbf + OFF_WC2, Wcat, 2048, 1024, 1024, nc);
    }

    // ---- encoder ----
    embed_k<<<dim3(SL, BA), 256>>>(src, embS, encx, SL);
    float* xin = encx; float* yout = ency;
    for (int l = 0; l < NL; l++) {
        gemm_tc_k<<<dim3(32, 7), 256>>>(xin, HID, eWih + (long)l*4096*1024, 1024,
                                        ebih + l*4096, ebhh + l*4096, encxg, 4096,
                                        SL*BA, 4096, 1024, 0, 0);
        float* hi = ehA; float* ho = ehB;
        const float* Whh = eWhh + (long)l*4096*512;
        for (int st = 0; st < SL; st++) {
            enc_fused_k<<<64, 256>>>(Whh, encxg, hi, ho, ecc, yout,
                                     h0 + (long)l*BA*HID, c0 + (long)l*BA*HID, st);
            float* tmp = hi; hi = ho; ho = tmp;
        }
        float* t = xin; xin = yout; yout = t;
    }
    float* hsrc = xin;

    // ---- decoder precompute ----
    embed_k<<<dim3(TL, BA), 256>>>(tgt, embD, demb, TL);
    gemm_tc_k<<<dim3(32, 7), 256>>>(demb, HID, d0Wih, 2048, d0bih, d0bhh,
                                    pre0, 4096, TL*BA, 4096, 1024, 0, 0);
    gemm_k<<<dim3(8, 7), 256>>>(hsrc, HID, Wattn, 1024, 0, nullptr, nullptr,
                                hAp, HID, SL*BA, 1024, 1024, 0, 0);
    dinit_k<<<NL*BA*HID/256, 256>>>(dhA, h0, dc, c0, htl);

    // ---- decoder loop ----
    float* hi = dhA; float* ho = dhB;
    for (int t = 0; t < TL; t++) {
        mmbf_k<<<512, 256>>>(wbf + OFF_W0H, wbf + OFF_W0R, htl, hi, part, 4096);
        dec_cell_k<<<64, 256>>>(part, pre0 + (long)t*BA*4096, nullptr, nullptr,
                                dc, ho);
        for (int i = 0; i < NL-1; i++) {
            mmbf_k<<<512, 256>>>(wbf + OFF_WIH + (long)i*4194304,
                                 wbf + OFF_WHH + (long)i*4194304,
                                 ho + (long)i*BA*HID,
                                 hi + (long)(i+1)*BA*HID, part, 4096);
            dec_cell_k<<<64, 256>>>(part, nullptr, dbih + i*4096, dbhh + i*4096,
                                    dc + (long)(i+1)*BA*HID, ho + (long)(i+1)*BA*HID);
        }
        attn_k<<<BA, 256>>>(ho + (long)3*BA*HID, hAp, hsrc, ctx);
        mmbf_k<<<128, 256>>>(wbf + OFF_WC1, wbf + OFF_WC2,
                             ho + (long)3*BA*HID, ctx, part, 1024);
        htanh_k<<<64, 256>>>(part, bcat, htl, hbt, t);
        float* tmp = hi; hi = ho; ho = tmp;
    }

    // ---- generator (tf32 tensor cores) ----
    gemm_tc_k<<<dim3(250, 7), 256>>>(hbt, HID, Wout, 1024, bout, nullptr,
                                     out, VOUT, TL*BA, VOUT, 1024, 1, 0);
    lsm_k<<<TL*BA, 256>>>(out);
}

// round 11
// speedup vs baseline: 1.4897x; 1.2074x over previous
#include <cuda_runtime.h>
#include <cuda_bf16.h>
#include <math.h>

#define SL 50
#define TL 50
#define BA 16
#define HID 1024
#define HD2 512
#define NL 4
#define VOUT 32000

__device__ __align__(16) float g_encx [SL*BA*HID];
__device__ __align__(16) float g_ency [SL*BA*HID];
__device__ __align__(16) float g_encxg[SL*BA*4096];
__device__ __align__(16) float g_enchA[2*BA*HD2];
__device__ __align__(16) float g_enchB[2*BA*HD2];
__device__ __align__(16) float g_encc [2*BA*HD2];
__device__ __align__(16) float g_h0   [NL*BA*HID];
__device__ __align__(16) float g_c0   [NL*BA*HID];
__device__ __align__(16) float g_demb [TL*BA*HID];
__device__ __align__(16) float g_pre0 [TL*BA*4096];
__device__ __align__(16) float g_dhA  [NL*BA*HID];
__device__ __align__(16) float g_dhB  [NL*BA*HID];
__device__ __align__(16) float g_dc   [NL*BA*HID];
__device__ __align__(16) float g_htl  [BA*HID];
__device__ __align__(16) float g_ctx  [BA*HID];
__device__ __align__(16) float g_hA   [SL*BA*HID];
__device__ __align__(16) float g_hbt  [TL*BA*HID];   // [t][b][H]
__device__ __align__(16) float g_part [16*4096*16];
__device__ int g_ctrs[512];
#define OFF_W0H 0L
#define OFF_W0R 4194304L
#define OFF_WIH 8388608L
#define OFF_WHH 20971520L
#define OFF_WC1 33554432L
#define OFF_WC2 34603008L
__device__ __align__(16) __nv_bfloat16 g_wbf[35651584];

__device__ __forceinline__ float sigf(float x){ return 1.f/(1.f+expf(-x)); }

__device__ __forceinline__ unsigned cvt_tf32(float f){
    unsigned u;
    asm("cvt.rna.tf32.f32 %0, %1;" : "=r"(u) : "f"(f));
    return u;
}

__global__ void ctrz_k(){ g_ctrs[threadIdx.x + blockIdx.x*256] = 0; }

__global__ void embed_k(const int* __restrict__ idx, const float* __restrict__ W,
                        float* __restrict__ out, int slen){
    int s = blockIdx.x, b = blockIdx.y;
    long tok = idx[b*slen + s];
    const float4* sp = (const float4*)(W + tok*1024);
    float4* dp = (float4*)(out + ((long)s*BA + b)*1024);
    for (int i = threadIdx.x; i < 256; i += blockDim.x) dp[i] = sp[i];
}

__global__ void dinit_k(float* __restrict__ dh, const float* __restrict__ h0,
                        float* __restrict__ dcc, const float* __restrict__ c0,
                        float* __restrict__ htl){
    int i = blockIdx.x*256 + threadIdx.x;
    dh[i] = h0[i];
    dcc[i] = c0[i];
    if (i < BA*HID) htl[i] = 0.f;
}

// fast contiguous fp32 -> bf16 (total4 = count of float4)
__global__ void cvtf_k(__nv_bfloat16* __restrict__ dst, const float* __restrict__ src,
                       long total4){
    long stride = (long)gridDim.x*blockDim.x;
    for (long i = (long)blockIdx.x*blockDim.x + threadIdx.x; i < total4; i += stride){
        float4 v = ((const float4*)src)[i];
        ((__nv_bfloat162*)dst)[2*i]   = __floats2bfloat162_rn(v.x, v.y);
        ((__nv_bfloat162*)dst)[2*i+1] = __floats2bfloat162_rn(v.z, v.w);
    }
}
// strided column-slice fp32 -> bf16
__global__ void cvt_k(__nv_bfloat16* __restrict__ dst, const float* __restrict__ src,
                      int srcld, int col0, int ncols, long total){
    long stride = (long)gridDim.x*blockDim.x;
    for (long i = (long)blockIdx.x*blockDim.x + threadIdx.x; i < total; i += stride){
        long r = i / ncols, cc = i - r*ncols;
        dst[i] = __float2bfloat16(src[r*srcld + col0 + cc]);
    }
}

// ---------- tf32 tensor-core GEMM: C = A[M,K] @ B[N,K]^T (+b1 +b2) ----------
__global__ __launch_bounds__(256) void gemm_tc_k(
    const float* __restrict__ A, int lda,
    const float* __restrict__ B, int ldb,
    const float* __restrict__ b1, const float* __restrict__ b2,
    float* __restrict__ C, int ldc, int M, int N, int K, int scat, int t0)
{
    __shared__ unsigned As[128][36];
    __shared__ unsigned Bs[128][36];
    int tid = threadIdx.x;
    int m0 = blockIdx.y*128, n0 = blockIdx.x*128;
    int warp = tid >> 5, lane = tid & 31;
    int wm = warp >> 2, wn = warp & 3;
    int g = lane >> 2, tg = lane & 3;
    float acc[4][4][4];
#pragma unroll
    for (int mt = 0; mt < 4; mt++)
#pragma unroll
        for (int nt = 0; nt < 4; nt++)
#pragma unroll
            for (int i = 0; i < 4; i++) acc[mt][nt][i] = 0.f;

    for (int k0 = 0; k0 < K; k0 += 32) {
#pragma unroll
        for (int i = 0; i < 4; i++) {
            int e = tid + i*256;
            int m = e >> 3, kq = e & 7;
            float4 v = make_float4(0,0,0,0);
            if (m0 + m < M) v = *(const float4*)(A + (long)(m0+m)*lda + k0 + kq*4);
            unsigned* d = &As[m][kq*4];
            d[0]=cvt_tf32(v.x); d[1]=cvt_tf32(v.y); d[2]=cvt_tf32(v.z); d[3]=cvt_tf32(v.w);
        }
#pragma unroll
        for (int i = 0; i < 4; i++) {
            int e = tid + i*256;
            int n = e >> 3, kq = e & 7;
            float4 v = *(const float4*)(B + (long)(n0+n)*ldb + k0 + kq*4);
            unsigned* d = &Bs[n][kq*4];
            d[0]=cvt_tf32(v.x); d[1]=cvt_tf32(v.y); d[2]=cvt_tf32(v.z); d[3]=cvt_tf32(v.w);
        }
        __syncthreads();
#pragma unroll
        for (int ks = 0; ks < 4; ks++) {
            int kb = ks*8;
            unsigned a[4][4], b[4][2];
#pragma unroll
            for (int mt = 0; mt < 4; mt++) {
                int mb = wm*64 + mt*16;
                a[mt][0] = As[mb+g  ][kb+tg];
                a[mt][1] = As[mb+g+8][kb+tg];
                a[mt][2] = As[mb+g  ][kb+tg+4];
                a[mt][3] = As[mb+g+8][kb+tg+4];
            }
#pragma unroll
            for (int nt = 0; nt < 4; nt++) {
                int nb = wn*32 + nt*8;
                b[nt][0] = Bs[nb+g][kb+tg];
                b[nt][1] = Bs[nb+g][kb+tg+4];
            }
#pragma unroll
            for (int mt = 0; mt < 4; mt++)
#pragma unroll
                for (int nt = 0; nt < 4; nt++)
                    asm volatile(
                        "mma.sync.aligned.m16n8k8.row.col.f32.tf32.tf32.f32 "
                        "{%0,%1,%2,%3}, {%4,%5,%6,%7}, {%8,%9}, {%0,%1,%2,%3};"
                        : "+f"(acc[mt][nt][0]), "+f"(acc[mt][nt][1]),
                          "+f"(acc[mt][nt][2]), "+f"(acc[mt][nt][3])
                        : "r"(a[mt][0]), "r"(a[mt][1]), "r"(a[mt][2]), "r"(a[mt][3]),
                          "r"(b[nt][0]), "r"(b[nt][1]));
        }
        __syncthreads();
    }
#pragma unroll
    for (int mt = 0; mt < 4; mt++) {
#pragma unroll
        for (int h = 0; h < 2; h++) {
            int m = m0 + wm*64 + mt*16 + g + h*8;
            if (m < M) {
                long crow = scat ? ((long)(m & 15)*TL + t0 + (m >> 4)) : (long)m;
#pragma unroll
                for (int nt = 0; nt < 4; nt++) {
                    int n = n0 + wn*32 + nt*8 + tg*2;
                    float v0 = acc[mt][nt][h*2+0];
                    float v1 = acc[mt][nt][h*2+1];
                    if (b1) { v0 += b1[n]; v1 += b1[n+1]; }
                    if (b2) { v0 += b2[n]; v1 += b2[n+1]; }
                    C[crow*ldc + n]     = v0;
                    C[crow*ldc + n + 1] = v1;
                }
            }
        }
    }
}

// ---------------- scalar fp32 GEMM (small hA GEMM only) ---------------------
__global__ __launch_bounds__(256) void gemm_k(
    const float* __restrict__ A, int lda,
    const float* __restrict__ B, int ldb, int transB,
    const float* __restrict__ b1, const float* __restrict__ b2,
    float* __restrict__ C, int ldc, int M, int N, int K)
{
    __shared__ float As[16][132];
    __shared__ float Bs[16][132];
    int m0 = blockIdx.y*128, n0 = blockIdx.x*128;
    int tid = threadIdx.x, tx = tid & 15, ty = tid >> 4;
    float acc[8][8];
#pragma unroll
    for (int i = 0; i < 8; i++)
#pragma unroll
        for (int j = 0; j < 8; j++) acc[i][j] = 0.f;

    for (int k0 = 0; k0 < K; k0 += 16) {
#pragma unroll
        for (int i = 0; i < 2; i++) {
            int e = tid + i*256, m = e >> 2, kq = e & 3;
            float4 v = make_float4(0,0,0,0);
            if (m0 + m < M) v = *(const float4*)(A + (long)(m0+m)*lda + k0 + kq*4);
            As[kq*4+0][m]=v.x; As[kq*4+1][m]=v.y; As[kq*4+2][m]=v.z; As[kq*4+3][m]=v.w;
        }
        if (transB) {
#pragma unroll
            for (int i = 0; i < 2; i++) {
                int e = tid + i*256, n = e >> 2, kq = e & 3;
                float4 v = *(const float4*)(B + (long)(n0+n)*ldb + k0 + kq*4);
                Bs[kq*4+0][n]=v.x; Bs[kq*4+1][n]=v.y; Bs[kq*4+2][n]=v.z; Bs[kq*4+3][n]=v.w;
            }
        } else {
#pragma unroll
            for (int i = 0; i < 2; i++) {
                int e = tid + i*256, kk = e >> 5, nq = e & 31;
                *(float4*)&Bs[kk][nq*4] = *(const float4*)(B + (long)(k0+kk)*ldb + n0 + nq*4);
            }
        }
        __syncthreads();
#pragma unroll
        for (int kk = 0; kk < 16; kk++) {
            float a[8], bv[8];
            *(float4*)&a[0] = *(float4*)&As[kk][ty*8];
            *(float4*)&a[4] = *(float4*)&As[kk][ty*8+4];
            *(float4*)&bv[0] = *(float4*)&Bs[kk][tx*8];
            *(float4*)&bv[4] = *(float4*)&Bs[kk][tx*8+4];
#pragma unroll
            for (int i = 0; i < 8; i++)
#pragma unroll
                for (int j = 0; j < 8; j++) acc[i][j] = fmaf(a[i], bv[j], acc[i][j]);
        }
        __syncthreads();
    }
#pragma unroll
    for (int i = 0; i < 8; i++) {
        int m = m0 + ty*8 + i;
        if (m < M) {
            float* Cr = C + (long)m*ldc + n0 + tx*8;
#pragma unroll
            for (int j = 0; j < 8; j++) {
                int n = n0 + tx*8 + j;
                float v = acc[i][j];
                if (b1) v += b1[n];
                if (b2) v += b2[n];
                Cr[j] = v;
            }
        }
    }
}

// ------- fused encoder step: 128 blocks (8 hd x 4 gates each), both dirs ----
__global__ __launch_bounds__(256) void enc_fused_k(
    const float* __restrict__ Whh, const float* __restrict__ xg,
    const float* __restrict__ hin, float* __restrict__ hout,
    float* __restrict__ c, float* __restrict__ y,
    float* __restrict__ h0l, float* __restrict__ c0l, int step)
{
    __shared__ __align__(16) float hs[512][18];
    __shared__ float sg[32][17];
    int tid = threadIdx.x;
    int dir = blockIdx.x >> 6, hgrp = blockIdx.x & 63;
    int s = dir ? (SL-1-step) : step;
    int r = tid >> 3, q = tid & 7;        // r: 32 gate-rows, q: batch pair
    float a0 = 0.f, a1 = 0.f;

    if (step > 0) {
        const float* hsrc = hin + dir*(BA*HD2);
#pragma unroll
        for (int i = 0; i < 32; i++) {
            int e = tid + i*256;
            hs[e & 511][e >> 9] = hsrc[e];
        }
        __syncthreads();
        int g = r >> 3, j = r & 7;
        const float* wr = Whh + ((long)dir*2048 + g*512 + hgrp*8 + j) * 512;
#pragma unroll 4
        for (int k = 0; k < 512; k += 8) {
            float w8[8];
            *(float4*)&w8[0] = *(const float4*)(wr + k);
            *(float4*)&w8[4] = *(const float4*)(wr + k + 4);
#pragma unroll
            for (int kk = 0; kk < 8; kk++) {
                float2 hv = *(const float2*)&hs[k+kk][2*q];
                a0 = fmaf(w8[kk], hv.x, a0);
                a1 = fmaf(w8[kk], hv.y, a1);
            }
        }
    }
    sg[r][2*q] = a0; sg[r][2*q+1] = a1;
    __syncthreads();

    if (tid < 128) {
        int j = tid >> 4, b = tid & 15;
        int hd = hgrp*8 + j;
        long xb = ((long)s*BA + b)*4096 + dir*2048 + hd;
        float gi = sg[j     ][b] + xg[xb];
        float gf = sg[8  + j][b] + xg[xb + 512];
        float gg = sg[16 + j][b] + xg[xb + 1024];
        float go = sg[24 + j][b] + xg[xb + 1536];
        int ci = dir*(BA*HD2) + b*HD2 + hd;
        float cc = step ? c[ci] : 0.f;
        float cn = sigf(gf)*cc + sigf(gi)*tanhf(gg);
        float hn = sigf(go)*tanhf(cn);
        c[ci] = cn; hout[ci] = hn;
        y[((long)s*BA + b)*HID + dir*512 + hd] = hn;
        if (step == SL-1) {
            h0l[b*HID + dir*512 + hd] = hn;
            c0l[b*HID + dir*512 + hd] = cn;
        }
    }
}

// -------- decoder layer: mm (512 blocks) + ticket-fused cell (+attn) --------
__global__ __launch_bounds__(256, 4) void mmbf_cell_k(
    const __nv_bfloat16* __restrict__ W1, const __nv_bfloat16* __restrict__ W2,
    const float* __restrict__ x1, const float* __restrict__ x2,
    const float* __restrict__ pre, const float* __restrict__ b1,
    const float* __restrict__ b2,
    float* __restrict__ c, float* __restrict__ hout,
    int* ctr1, int* ctr2,
    const float* __restrict__ hA, const float* __restrict__ hsrc,
    float* __restrict__ ctx)
{
    __shared__ __align__(16) __nv_bfloat16 Wt[128][136];
    __shared__ __align__(16) float xs[128][20];
    __shared__ int tick;
    int tid = threadIdx.x, bid = blockIdx.x;
    float* part = g_part;

    // ---- mm stage ----
    {
        int slice = bid & 15, rg = bid >> 4;
        int r0 = rg*128, k0 = slice*128;
        const __nv_bfloat16* W; const float* x; int ko;
        if (k0 < 1024) { W = W1; x = x1; ko = k0; }
        else           { W = W2; x = x2; ko = k0 - 1024; }
        uint4 wc[8];
        float xr[8];
#pragma unroll
        for (int i = 0; i < 8; i++) {
            int cidx = tid + i*256;
            int row = cidx >> 4, qq = cidx & 15;
            wc[i] = *(const uint4*)(W + (long)(r0+row)*1024 + ko + qq*8);
        }
#pragma unroll
        for (int i = 0; i < 8; i++) {
            int e = tid + i*256;
            int b = e >> 7, kk = e & 127;
            xr[i] = __ldcg(x + b*1024 + ko + kk);
        }
#pragma unroll
        for (int i = 0; i < 8; i++) {
            int cidx = tid + i*256;
            int row = cidx >> 4, qq = cidx & 15;
            *(uint4*)&Wt[row][qq*8] = wc[i];
        }
#pragma unroll
        for (int i = 0; i < 8; i++) {
            int e = tid + i*256;
            int b = e >> 7, kk = e & 127;
            xs[kk][b] = xr[i];
        }
        __syncthreads();
        int rp = tid >> 2, bq = tid & 3;
        float a00=0,a01=0,a02=0,a03=0,a10=0,a11=0,a12=0,a13=0;
#pragma unroll 8
        for (int k = 0; k < 128; k += 2) {
            __nv_bfloat162 wa = *(const __nv_bfloat162*)&Wt[2*rp  ][k];
            __nv_bfloat162 wb = *(const __nv_bfloat162*)&Wt[2*rp+1][k];
            float2 fa = __bfloat1622float2(wa);
            float2 fb = __bfloat1622float2(wb);
            float4 x0 = *(const float4*)&xs[k  ][4*bq];
            float4 x1v = *(const float4*)&xs[k+1][4*bq];
            a00 = fmaf(fa.x, x0.x, a00); a01 = fmaf(fa.x, x0.y, a01);
            a02 = fmaf(fa.x, x0.z, a02); a03 = fmaf(fa.x, x0.w, a03);
            a10 = fmaf(fb.x, x0.x, a10); a11 = fmaf(fb.x, x0.y, a11);
            a12 = fmaf(fb.x, x0.z, a12); a13 = fmaf(fb.x, x0.w, a13);
            a00 = fmaf(fa.y, x1v.x, a00); a01 = fmaf(fa.y, x1v.y, a01);
            a02 = fmaf(fa.y, x1v.z, a02); a03 = fmaf(fa.y, x1v.w, a03);
            a10 = fmaf(fb.y, x1v.x, a10); a11 = fmaf(fb.y, x1v.y, a11);
            a12 = fmaf(fb.y, x1v.z, a12); a13 = fmaf(fb.y, x1v.w, a13);
        }
        float* p = part + ((long)slice*4096 + r0 + 2*rp)*16 + 4*bq;
        *(float4*)p        = make_float4(a00,a01,a02,a03);
        *(float4*)(p + 16) = make_float4(a10,a11,a12,a13);
    }

    // ---- ticket: last 64 arrivals do the LSTM cell ----
    __threadfence();
    if (tid == 0) tick = atomicAdd(ctr1, 1);
    __syncthreads();
    int ticket = tick;
    if (ticket < 512 - 64) return;
    if (tid == 0) { while (*(volatile int*)ctr1 < 512) ; }
    __syncthreads();
    {
        int idx = (ticket - 448)*256 + tid;
        int b = idx & 15, hd = idx >> 4;
        float g[4];
#pragma unroll
        for (int gi = 0; gi < 4; gi++) {
            int row = gi*HID + hd;
            float v;
            if (pre) v = pre[(long)b*4096 + row];
            else     v = b1[row] + b2[row];
#pragma unroll
            for (int sl = 0; sl < 16; sl++)
                v += __ldcg(part + ((long)sl*4096 + row)*16 + b);
            g[gi] = v;
        }
        int ci = b*HID + hd;
        float cc = c[ci];
        float cn = sigf(g[1])*cc + sigf(g[0])*tanhf(g[2]);
        c[ci] = cn;
        hout[ci] = sigf(g[3])*tanhf(cn);
    }
    if (!ctr2) return;

    // ---- ticket 2: last 16 of the 64 cell blocks do attention ----
    __threadfence();
    __syncthreads();
    if (tid == 0) tick = atomicAdd(ctr2, 1);
    __syncthreads();
    int t2 = tick;
    if (t2 < 64 - 16) return;
    if (tid == 0) { while (*(volatile int*)ctr2 < 64) ; }
    __syncthreads();
    {
        int b = t2 - 48;
        float* h3s = (float*)&Wt[0][0];
        float* sc  = h3s + 1024;
        for (int i = tid; i < HID; i += 256) h3s[i] = __ldcg(hout + b*HID + i);
        __syncthreads();
        int w = tid >> 5, lane = tid & 31;
        for (int s = w; s < SL; s += 8) {
            const float* hp = hA + ((long)s*BA + b)*HID;
            float p = 0.f;
            for (int k = lane; k < HID; k += 32) p = fmaf(h3s[k], hp[k], p);
#pragma unroll
            for (int o = 16; o > 0; o >>= 1) p += __shfl_xor_sync(0xffffffffu, p, o);
            if (lane == 0) sc[s] = p;
        }
        __syncthreads();
        if (tid == 0) {
            float mx = sc[0];
            for (int s = 1; s < SL; s++) mx = fmaxf(mx, sc[s]);
            float sum = 0.f;
            for (int s = 0; s < SL; s++) { sc[s] = expf(sc[s]-mx); sum += sc[s]; }
            float inv = 1.f/sum;
            for (int s = 0; s < SL; s++) sc[s] *= inv;
        }
        __syncthreads();
        float4 acc = make_float4(0,0,0,0);
        int k = tid*4;
        for (int s = 0; s < SL; s++) {
            float ws = sc[s];
            float4 v = *(const float4*)(hsrc + ((long)s*BA + b)*HID + k);
            acc.x = fmaf(ws, v.x, acc.x); acc.y = fmaf(ws, v.y, acc.y);
            acc.z = fmaf(ws, v.z, acc.z); acc.w = fmaf(ws, v.w, acc.w);
        }
        *(float4*)(ctx + b*HID + k) = acc;
    }
}

// -------- h_tilde: mm (128 blocks, rtot=1024) + ticket-fused tanh ----------
__global__ __launch_bounds__(256, 4) void mmbf_ht_k(
    const __nv_bfloat16* __restrict__ W1, const __nv_bfloat16* __restrict__ W2,
    const float* __restrict__ x1, const float* __restrict__ x2,
    const float* __restrict__ bc,
    float* __restrict__ htl, float* __restrict__ hbt, int t, int* ctr1)
{
    __shared__ __align__(16) __nv_bfloat16 Wt[128][136];
    __shared__ __align__(16) float xs[128][20];
    __shared__ int tick;
    int tid = threadIdx.x, bid = blockIdx.x;
    float* part = g_part;
    {
        int slice = bid & 15, rg = bid >> 4;
        int r0 = rg*128, k0 = slice*128;
        const __nv_bfloat16* W; const float* x; int ko;
        if (k0 < 1024) { W = W1; x = x1; ko = k0; }
        else           { W = W2; x = x2; ko = k0 - 1024; }
        uint4 wc[8];
        float xr[8];
#pragma unroll
        for (int i = 0; i < 8; i++) {
            int cidx = tid + i*256;
            int row = cidx >> 4, qq = cidx & 15;
            wc[i] = *(const uint4*)(W + (long)(r0+row)*1024 + ko + qq*8);
        }
#pragma unroll
        for (int i = 0; i < 8; i++) {
            int e = tid + i*256;
            int b = e >> 7, kk = e & 127;
            xr[i] = __ldcg(x + b*1024 + ko + kk);
        }
#pragma unroll
        for (int i = 0; i < 8; i++) {
            int cidx = tid + i*256;
            int row = cidx >> 4, qq = cidx & 15;
            *(uint4*)&Wt[row][qq*8] = wc[i];
        }
#pragma unroll
        for (int i = 0; i < 8; i++) {
            int e = tid + i*256;
            int b = e >> 7, kk = e & 127;
            xs[kk][b] = xr[i];
        }
        __syncthreads();
        int rp = tid >> 2, bq = tid & 3;
        float a00=0,a01=0,a02=0,a03=0,a10=0,a11=0,a12=0,a13=0;
#pragma unroll 8
        for (int k = 0; k < 128; k += 2) {
            __nv_bfloat162 wa = *(const __nv_bfloat162*)&Wt[2*rp  ][k];
            __nv_bfloat162 wb = *(const __nv_bfloat162*)&Wt[2*rp+1][k];
            float2 fa = __bfloat1622float2(wa);
            float2 fb = __bfloat1622float2(wb);
            float4 x0 = *(const float4*)&xs[k  ][4*bq];
            float4 x1v = *(const float4*)&xs[k+1][4*bq];
            a00 = fmaf(fa.x, x0.x, a00); a01 = fmaf(fa.x, x0.y, a01);
            a02 = fmaf(fa.x, x0.z, a02); a03 = fmaf(fa.x, x0.w, a03);
            a10 = fmaf(fb.x, x0.x, a10); a11 = fmaf(fb.x, x0.y, a11);
            a12 = fmaf(fb.x, x0.z, a12); a13 = fmaf(fb.x, x0.w, a13);
            a00 = fmaf(fa.y, x1v.x, a00); a01 = fmaf(fa.y, x1v.y, a01);
            a02 = fmaf(fa.y, x1v.z, a02); a03 = fmaf(fa.y, x1v.w, a03);
            a10 = fmaf(fb.y, x1v.x, a10); a11 = fmaf(fb.y, x1v.y, a11);
            a12 = fmaf(fb.y, x1v.z, a12); a13 = fmaf(fb.y, x1v.w, a13);
        }
        float* p = part + ((long)slice*1024 + r0 + 2*rp)*16 + 4*bq;
        *(float4*)p        = make_float4(a00,a01,a02,a03);
        *(float4*)(p + 16) = make_float4(a10,a11,a12,a13);
    }
    __threadfence();
    if (tid == 0) tick = atomicAdd(ctr1, 1);
    __syncthreads();
    int ticket = tick;
    if (ticket < 128 - 64) return;
    if (tid == 0) { while (*(volatile int*)ctr1 < 128) ; }
    __syncthreads();
    {
        int idx = (ticket - 64)*256 + tid;
        int b = idx & 15, hd = idx >> 4;
        float v = bc[hd];
#pragma unroll
        for (int sl = 0; sl < 16; sl++)
            v += __ldcg(part + ((long)sl*1024 + hd)*16 + b);
        float h = tanhf(v);
        htl[b*HID + hd] = h;
        hbt[((long)t*BA + b)*HID + hd] = h;
    }
}

// ---------------- log-softmax ----------------
__global__ __launch_bounds__(256) void lsm_k(float* __restrict__ out)
{
    __shared__ float red[256];
    long m = blockIdx.x;
    float* row = out + m*VOUT;
    int tid = threadIdx.x;
    float mx = -1e30f;
    for (int i = tid; i < VOUT/4; i += 256) {
        float4 v = *(const float4*)(row + i*4);
        mx = fmaxf(mx, fmaxf(fmaxf(v.x, v.y), fmaxf(v.z, v.w)));
    }
    red[tid] = mx; __syncthreads();
    for (int o = 128; o > 0; o >>= 1) { if (tid < o) red[tid] = fmaxf(red[tid], red[tid+o]); __syncthreads(); }
    mx = red[0]; __syncthreads();
    float sum = 0.f;
    for (int i = tid; i < VOUT/4; i += 256) {
        float4 v = *(const float4*)(row + i*4);
        sum += expf(v.x-mx)+expf(v.y-mx)+expf(v.z-mx)+expf(v.w-mx);
    }
    red[tid] = sum; __syncthreads();
    for (int o = 128; o > 0; o >>= 1) { if (tid < o) red[tid] += red[tid+o]; __syncthreads(); }
    float lse = mx + logf(red[0]);
    for (int i = tid; i < VOUT/4; i += 256) {
        float4 v = *(const float4*)(row + i*4);
        v.x -= lse; v.y -= lse; v.z -= lse; v.w -= lse;
        *(float4*)(row + i*4) = v;
    }
}

static float* sym(const void* s){ void* p = nullptr; cudaGetSymbolAddress(&p, s); return (float*)p; }

extern "C" void kernel_launch(void* const* d_in, const int* in_sizes, int n_in,
                              void* d_out, int out_size)
{
    const int*   src   = (const int*)  d_in[0];
    const int*   tgt   = (const int*)  d_in[1];
    const float* embS  = (const float*)d_in[2];
    const float* embD  = (const float*)d_in[3];
    const float* eWih  = (const float*)d_in[4];
    const float* eWhh  = (const float*)d_in[5];
    const float* ebih  = (const float*)d_in[6];
    const float* ebhh  = (const float*)d_in[7];
    const float* d0Wih = (const float*)d_in[8];
    const float* d0Whh = (const float*)d_in[9];
    const float* d0bih = (const float*)d_in[10];
    const float* d0bhh = (const float*)d_in[11];
    const float* dWih  = (const float*)d_in[12];
    const float* dWhh  = (const float*)d_in[13];
    const float* dbih  = (const float*)d_in[14];
    const float* dbhh  = (const float*)d_in[15];
    const float* Wattn = (const float*)d_in[16];
    const float* Wcat  = (const float*)d_in[17];
    const float* bcat  = (const float*)d_in[18];
    const float* Wout  = (const float*)d_in[19];
    const float* bout  = (const float*)d_in[20];
    float* out = (float*)d_out;

    float* encx = sym(g_encx);  float* ency = sym(g_ency);
    float* encxg = sym(g_encxg);
    float* ehA = sym(g_enchA);  float* ehB = sym(g_enchB);
    float* ecc = sym(g_encc);
    float* h0 = sym(g_h0);      float* c0 = sym(g_c0);
    float* demb = sym(g_demb);  float* pre0 = sym(g_pre0);
    float* dhA = sym(g_dhA);    float* dhB = sym(g_dhB);
    float* dc  = sym(g_dc);
    float* htl = sym(g_htl);    float* ctx = sym(g_ctx);
    float* hAp = sym(g_hA);     float* hbt = sym(g_hbt);
    __nv_bfloat16* wbf = (__nv_bfloat16*)sym(g_wbf);
    int* ctrs = (int*)sym(g_ctrs);

    ctrz_k<<<2, 256>>>();

    // ---- bf16 weight conversion ----
    {
        long n1 = 4194304L, n3 = 12582912L, nc = 1048576L;
        cvt_k <<<1024, 256>>>(wbf + OFF_W0H, d0Wih, 2048, 1024, 1024, n1);
        cvtf_k<<<1024, 256>>>(wbf + OFF_W0R, d0Whh, n1/4);
        cvtf_k<<<2048, 256>>>(wbf + OFF_WIH, dWih, n3/4);
        cvtf_k<<<2048, 256>>>(wbf + OFF_WHH, dWhh, n3/4);
        cvt_k <<<512, 256>>>(wbf + OFF_WC1, Wcat, 2048, 0, 1024, nc);
        cvt_k <<<512, 256>>>(wbf + OFF_WC2, Wcat, 2048, 1024, 1024, nc);
    }

    // ---- encoder ----
    embed_k<<<dim3(SL, BA), 256>>>(src, embS, encx, SL);
    float* xin = encx; float* yout = ency;
    for (int l = 0; l < NL; l++) {
        gemm_tc_k<<<dim3(32, 7), 256>>>(xin, HID, eWih + (long)l*4096*1024, 1024,
                                        ebih + l*4096, ebhh + l*4096, encxg, 4096,
                                        SL*BA, 4096, 1024, 0, 0);
        float* hi = ehA; float* ho = ehB;
        const float* Whh = eWhh + (long)l*4096*512;
        for (int st = 0; st < SL; st++) {
            enc_fused_k<<<128, 256>>>(Whh, encxg, hi, ho, ecc, yout,
                                      h0 + (long)l*BA*HID, c0 + (long)l*BA*HID, st);
            float* tmp = hi; hi = ho; ho = tmp;
        }
        float* t = xin; xin = yout; yout = t;
    }
    float* hsrc = xin;

    // ---- decoder precompute ----
    embed_k<<<dim3(TL, BA), 256>>>(tgt, embD, demb, TL);
    gemm_tc_k<<<dim3(32, 7), 256>>>(demb, HID, d0Wih, 2048, d0bih, d0bhh,
                                    pre0, 4096, TL*BA, 4096, 1024, 0, 0);
    gemm_k<<<dim3(8, 7), 256>>>(hsrc, HID, Wattn, 1024, 0, nullptr, nullptr,
                                hAp, HID, SL*BA, 1024, 1024);
    dinit_k<<<NL*BA*HID/256, 256>>>(dhA, h0, dc, c0, htl);

    // ---- decoder loop: 5 kernels/step ----
    for (int t = 0; t < TL; t++) {
        float* hprev = (t & 1) ? dhB : dhA;
        float* hcur  = (t & 1) ? dhA : dhB;
        mmbf_cell_k<<<512, 256>>>(wbf + OFF_W0H, wbf + OFF_W0R, htl, hprev,
                                  pre0 + (long)t*BA*4096, nullptr, nullptr,
                                  dc, hcur,
                                  ctrs + t*6 + 0, nullptr, nullptr, nullptr, nullptr);
        for (int i = 0; i < NL-1; i++) {
            int last = (i == NL-2);
            mmbf_cell_k<<<512, 256>>>(wbf + OFF_WIH + (long)i*4194304,
                                      wbf + OFF_WHH + (long)i*4194304,
                                      hcur + (long)i*BA*HID,
                                      hprev + (long)(i+1)*BA*HID,
                                      nullptr, dbih + i*4096, dbhh + i*4096,
                                      dc + (long)(i+1)*BA*HID,
                                      hcur + (long)(i+1)*BA*HID,
                                      ctrs + t*6 + 1 + i,
                                      last ? (ctrs + t*6 + 5) : nullptr,
                                      last ? hAp : nullptr,
                                      last ? hsrc : nullptr,
                                      last ? ctx : nullptr);
        }
        mmbf_ht_k<<<128, 256>>>(wbf + OFF_WC1, wbf + OFF_WC2,
                                hcur + (long)3*BA*HID, ctx,
                                bcat, htl, hbt, t, ctrs + t*6 + 4);
    }

    // ---- generator (tf32 tensor cores) ----
    gemm_tc_k<<<dim3(250, 7), 256>>>(hbt, HID, Wout, 1024, bout, nullptr,
                                     out, VOUT, TL*BA, VOUT, 1024, 1, 0);
    lsm_k<<<TL*BA, 256>>>(out);
}